// round 1
// baseline (speedup 1.0000x reference)
#include <cuda_runtime.h>

// Problem constants
#define Bsz   64
#define Tlen  2048
#define HID   512
#define HCLS  1024
#define DOUT  10

// GEMM tiling
#define BM 64
#define BN 64
#define BK 16

// Scratch (no cudaMalloc allowed)
__device__ float g_scores[Bsz * Tlen];     // [B,T] attention logits
__device__ float g_rowmax[Bsz];
__device__ float g_rowsum[Bsz];
__device__ float g_ctx[Bsz * HID];         // attention-pooled context

__device__ __forceinline__ float fast_tanh(float x) {
    x = fminf(fmaxf(x, -15.f), 15.f);
    float e = __expf(2.f * x);
    return __fdividef(e - 1.f, e + 1.f);
}

// ---------------------------------------------------------------------------
// Kernel 1: fused  scores[b,t] = tanh( sum_c tanh( emb[b,t,:]@W[:,c] + bias[c] ) * cw[c] )
// Tiled fp32 GEMM, epilogue reduces over columns so u is never materialized.
// grid = (B*T)/BM blocks, 256 threads.
// ---------------------------------------------------------------------------
__global__ __launch_bounds__(256) void scores_kernel(
    const float* __restrict__ emb,     // [B*T, HID]
    const float* __restrict__ W,       // [HID, HID]  (u = emb @ W)
    const float* __restrict__ bias,    // [HID]
    const float* __restrict__ cw)      // [HID]
{
    __shared__ float sA[BK][BM + 4];   // emb tile, transposed
    __shared__ float sB[BK][BN];       // W tile
    __shared__ float rs[BM];           // per-row reduced sums

    const int t    = threadIdx.x;           // 0..255
    const int row0 = blockIdx.x * BM;
    const int ty   = t >> 4;                // 0..15
    const int tx   = t & 15;                // 0..15
    const int m0   = ty * 4;
    const int n0   = tx * 4;

    // A-load mapping: 64x16 tile, each thread one float4 along k
    const int am = t >> 2;                  // 0..63
    const int ak = (t & 3) * 4;             // 0,4,8,12
    // B-load mapping: 16x64 tile, each thread one float4 along n
    const int bk = t >> 4;                  // 0..15
    const int bn = (t & 15) * 4;

    for (int i = t; i < BM; i += 256) rs[i] = 0.f;

    for (int cp = 0; cp < HID / BN; ++cp) {
        const int col0 = cp * BN;
        float acc[4][4] = {};

        for (int kk = 0; kk < HID; kk += BK) {
            __syncthreads();
            float4 av = *reinterpret_cast<const float4*>(
                &emb[(size_t)(row0 + am) * HID + kk + ak]);
            sA[ak + 0][am] = av.x;
            sA[ak + 1][am] = av.y;
            sA[ak + 2][am] = av.z;
            sA[ak + 3][am] = av.w;
            *reinterpret_cast<float4*>(&sB[bk][bn]) =
                *reinterpret_cast<const float4*>(
                    &W[(size_t)(kk + bk) * HID + col0 + bn]);
            __syncthreads();

            #pragma unroll
            for (int k = 0; k < BK; ++k) {
                float4 a = *reinterpret_cast<const float4*>(&sA[k][m0]);
                float4 b = *reinterpret_cast<const float4*>(&sB[k][n0]);
                float ar[4] = {a.x, a.y, a.z, a.w};
                float br[4] = {b.x, b.y, b.z, b.w};
                #pragma unroll
                for (int i = 0; i < 4; ++i)
                    #pragma unroll
                    for (int j = 0; j < 4; ++j)
                        acc[i][j] += ar[i] * br[j];
            }
        }

        // Epilogue: tanh(acc + bias)*cw, reduce over this block's 4 columns
        float rp[4] = {0.f, 0.f, 0.f, 0.f};
        #pragma unroll
        for (int j = 0; j < 4; ++j) {
            const int c = col0 + n0 + j;
            const float bc = __ldg(&bias[c]);
            const float wc = __ldg(&cw[c]);
            #pragma unroll
            for (int i = 0; i < 4; ++i)
                rp[i] += fast_tanh(acc[i][j] + bc) * wc;
        }
        #pragma unroll
        for (int i = 0; i < 4; ++i)
            atomicAdd(&rs[m0 + i], rp[i]);
    }

    __syncthreads();
    for (int i = t; i < BM; i += 256)
        g_scores[row0 + i] = fast_tanh(rs[i]);
}

// ---------------------------------------------------------------------------
// Kernel 2a: per-batch softmax stats (max + sumexp) over T; also zero g_ctx.
// grid = B, 256 threads.
// ---------------------------------------------------------------------------
__global__ __launch_bounds__(256) void stats_kernel()
{
    const int b = blockIdx.x;
    const int t = threadIdx.x;
    __shared__ float red[256];

    float m = -1e30f;
    for (int i = t; i < Tlen; i += 256) m = fmaxf(m, g_scores[b * Tlen + i]);
    red[t] = m; __syncthreads();
    for (int s = 128; s > 0; s >>= 1) {
        if (t < s) red[t] = fmaxf(red[t], red[t + s]);
        __syncthreads();
    }
    const float mx = red[0];
    __syncthreads();

    float sum = 0.f;
    for (int i = t; i < Tlen; i += 256) sum += __expf(g_scores[b * Tlen + i] - mx);
    red[t] = sum; __syncthreads();
    for (int s = 128; s > 0; s >>= 1) {
        if (t < s) red[t] += red[t + s];
        __syncthreads();
    }
    if (t == 0) { g_rowmax[b] = mx; g_rowsum[b] = red[0]; }

    for (int i = t; i < HID; i += 256) g_ctx[b * HID + i] = 0.f;
}

// ---------------------------------------------------------------------------
// Kernel 2b: ctx[b,h] += sum_{t in chunk} attn[b,t] * emb[b,t,h]
// grid = (B, 4), 512 threads (one per h). Coalesced emb reads.
// ---------------------------------------------------------------------------
#define TCHUNKS 4
#define TPC (Tlen / TCHUNKS)   // 512

__global__ __launch_bounds__(512) void ctx_kernel(const float* __restrict__ emb)
{
    const int b  = blockIdx.x;
    const int ck = blockIdx.y;
    const int h  = threadIdx.x;        // 0..511
    __shared__ float wsh[TPC];

    const int t0 = ck * TPC;
    const float mx  = g_rowmax[b];
    const float inv = __frcp_rn(g_rowsum[b]);
    wsh[h] = __expf(g_scores[b * Tlen + t0 + h] - mx) * inv;
    __syncthreads();

    float acc = 0.f;
    const float* e = emb + ((size_t)b * Tlen + t0) * HID + h;
    #pragma unroll 8
    for (int tt = 0; tt < TPC; ++tt)
        acc += wsh[tt] * e[(size_t)tt * HID];

    atomicAdd(&g_ctx[b * HID + h], acc);
}

// ---------------------------------------------------------------------------
// Kernel 3: classifier  softmax(relu(ctx@W1+b1)@W2 + b2). grid = B, 256 thr.
// ---------------------------------------------------------------------------
__global__ __launch_bounds__(256) void classifier_kernel(
    const float* __restrict__ W1, const float* __restrict__ b1,
    const float* __restrict__ W2, const float* __restrict__ b2,
    float* __restrict__ out)
{
    const int b = blockIdx.x;
    const int t = threadIdx.x;
    __shared__ float sc[HID];
    __shared__ float sh[HCLS];
    __shared__ float red[256];
    __shared__ float logits[DOUT];

    for (int i = t; i < HID; i += 256) sc[i] = g_ctx[b * HID + i];
    __syncthreads();

    for (int j = t; j < HCLS; j += 256) {
        float a = __ldg(&b1[j]);
        #pragma unroll 4
        for (int h = 0; h < HID; ++h)
            a += sc[h] * W1[(size_t)h * HCLS + j];
        sh[j] = fmaxf(a, 0.f);
    }
    __syncthreads();

    for (int o = 0; o < DOUT; ++o) {
        float p = 0.f;
        for (int j = t; j < HCLS; j += 256)
            p += sh[j] * W2[(size_t)j * DOUT + o];
        red[t] = p; __syncthreads();
        for (int s = 128; s > 0; s >>= 1) {
            if (t < s) red[t] += red[t + s];
            __syncthreads();
        }
        if (t == 0) logits[o] = red[0] + __ldg(&b2[o]);
        __syncthreads();
    }

    if (t == 0) {
        float mx = -1e30f;
        #pragma unroll
        for (int o = 0; o < DOUT; ++o) mx = fmaxf(mx, logits[o]);
        float s = 0.f, ex[DOUT];
        #pragma unroll
        for (int o = 0; o < DOUT; ++o) { ex[o] = __expf(logits[o] - mx); s += ex[o]; }
        const float inv = 1.f / s;
        #pragma unroll
        for (int o = 0; o < DOUT; ++o) out[b * DOUT + o] = ex[o] * inv;
    }
}

// ---------------------------------------------------------------------------
// Launch. Input order (metadata): numerical, embedding, weight, bias,
// context_weight, W1, b1, W2, b2.  Output: [B, DOUT] float32.
// ---------------------------------------------------------------------------
extern "C" void kernel_launch(void* const* d_in, const int* in_sizes, int n_in,
                              void* d_out, int out_size)
{
    (void)in_sizes; (void)n_in; (void)out_size;
    const float* emb  = (const float*)d_in[1];
    const float* W    = (const float*)d_in[2];
    const float* bias = (const float*)d_in[3];
    const float* cw   = (const float*)d_in[4];
    const float* W1   = (const float*)d_in[5];
    const float* b1   = (const float*)d_in[6];
    const float* W2   = (const float*)d_in[7];
    const float* b2   = (const float*)d_in[8];
    float* out = (float*)d_out;

    scores_kernel<<<(Bsz * Tlen) / BM, 256>>>(emb, W, bias, cw);
    stats_kernel<<<Bsz, 256>>>();
    ctx_kernel<<<dim3(Bsz, TCHUNKS), 512>>>(emb);
    classifier_kernel<<<Bsz, 256>>>(W1, b1, W2, b2, out);
}

// round 3
// speedup vs baseline: 2.3955x; 2.3955x over previous
#include <cuda_runtime.h>
#include <cuda_bf16.h>
#include <cstdint>

// ---------------- problem constants ----------------
#define Bsz   64
#define Tlen  2048
#define HID   512
#define HCLS  1024
#define DOUT  10

// ---------------- GEMM tiling ----------------
#define MT    64          // rows per CTA
#define NCH   128         // N per chunk (4 chunks cover 512)
#define KCH   64          // K per cp.async chunk

// ---------------- device scratch ----------------
__device__ __align__(16) __nv_bfloat16 g_Wt_hi[HID][HID];   // W^T hi plane [n][k]
__device__ __align__(16) __nv_bfloat16 g_Wt_lo[HID][HID];   // W^T lo plane [n][k]
__device__ float g_scores[Bsz * Tlen];
__device__ float g_rowmax[Bsz];
__device__ float g_rowsum[Bsz];
__device__ float g_ctx[Bsz * HID];
__device__ float g_hidden[Bsz * HCLS];

// ---------------- SMEM layout (dynamic) ----------------
#define SM_AHI   0
#define SM_ALO   65536
#define SM_B     131072                 // 2 buffers x (2 planes x 16384) = 65536
#define SM_BIAS  196608
#define SM_CW    198656
#define SM_RS    200704
#define SM_TOTAL 200960

// ---------------- helpers ----------------
__device__ __forceinline__ float fast_tanh(float x) {
    x = fminf(fmaxf(x, -15.f), 15.f);
    float e = __expf(2.f * x);
    return __fdividef(e - 1.f, e + 1.f);
}

__device__ __forceinline__ uint32_t smem_u32(const void* p) {
    uint32_t a;
    asm("{ .reg .u64 t; cvta.to.shared.u64 t, %1; cvt.u32.u64 %0, t; }" : "=r"(a) : "l"(p));
    return a;
}

__device__ __forceinline__ void ldsm_x4(uint32_t* r, uint32_t addr) {
    asm volatile("ldmatrix.sync.aligned.m8n8.x4.shared.b16 {%0,%1,%2,%3}, [%4];"
                 : "=r"(r[0]), "=r"(r[1]), "=r"(r[2]), "=r"(r[3]) : "r"(addr));
}
__device__ __forceinline__ void ldsm_x2(uint32_t* r, uint32_t addr) {
    asm volatile("ldmatrix.sync.aligned.m8n8.x2.shared.b16 {%0,%1}, [%2];"
                 : "=r"(r[0]), "=r"(r[1]) : "r"(addr));
}
__device__ __forceinline__ void mma_bf16(float* d, const uint32_t* a, const uint32_t* b) {
    asm volatile("mma.sync.aligned.m16n8k16.row.col.f32.bf16.bf16.f32 "
                 "{%0,%1,%2,%3}, {%4,%5,%6,%7}, {%8,%9}, {%0,%1,%2,%3};"
                 : "+f"(d[0]), "+f"(d[1]), "+f"(d[2]), "+f"(d[3])
                 : "r"(a[0]), "r"(a[1]), "r"(a[2]), "r"(a[3]), "r"(b[0]), "r"(b[1]));
}
__device__ __forceinline__ void cp16(uint32_t dst, const void* gsrc) {
    uint64_t g = __cvta_generic_to_global((void*)gsrc);
    asm volatile("cp.async.ca.shared.global [%0], [%1], 16;" :: "r"(dst), "l"(g) : "memory");
}
#define CP_COMMIT() asm volatile("cp.async.commit_group;" ::: "memory")
#define CP_WAIT0()  asm volatile("cp.async.wait_group 0;" ::: "memory")
#define CP_WAIT1()  asm volatile("cp.async.wait_group 1;" ::: "memory")

// ---------------------------------------------------------------------------
// Prep: W[k][n] fp32 -> W^T[n][k] split into bf16 hi/lo planes.
// ---------------------------------------------------------------------------
__global__ __launch_bounds__(512) void prep_kernel(const float* __restrict__ W)
{
    int idx = blockIdx.x * 512 + threadIdx.x;   // 0..262143
    int n = idx & 511;
    int k = idx >> 9;
    float w = W[(size_t)k * HID + n];
    __nv_bfloat16 hi = __float2bfloat16(w);
    __nv_bfloat16 lo = __float2bfloat16(w - __bfloat162float(hi));
    g_Wt_hi[n][k] = hi;
    g_Wt_lo[n][k] = lo;
}

// ---------------------------------------------------------------------------
// Scores: 64 rows/CTA, mma.sync bf16 hi/lo 3-pass, fused tanh-dot-tanh epilogue.
// 256 threads = 8 warps as 2(M) x 4(N); warp tile 32x32 (2 m16 x 4 n8).
// ---------------------------------------------------------------------------
__global__ __launch_bounds__(256, 1) void scores_kernel(
    const float* __restrict__ emb,
    const float* __restrict__ bias,
    const float* __restrict__ cw)
{
    extern __shared__ char smem[];
    const uint32_t sb = smem_u32(smem);
    const int t    = threadIdx.x;
    const int wid  = t >> 5;
    const int lane = t & 31;
    const int warpM = wid >> 2;      // 0..1
    const int warpN = wid & 3;       // 0..3
    const int row0 = blockIdx.x * MT;

    float* sbias = (float*)(smem + SM_BIAS);
    float* scw   = (float*)(smem + SM_CW);
    float* rs    = (float*)(smem + SM_RS);

    for (int i = t; i < HID; i += 256) { sbias[i] = bias[i]; scw[i] = cw[i]; }
    if (t < MT) rs[t] = 0.f;

    // ---- A: load 64x512 fp32, split bf16 hi/lo, store swizzled (once) ----
    for (int task = t; task < MT * 64; task += 256) {
        int row = task >> 6;
        int c   = task & 63;                     // 16B chunk (8 bf16)
        const float4* src = (const float4*)&emb[(size_t)(row0 + row) * HID + c * 8];
        float4 v0 = src[0], v1 = src[1];
        float x[8] = {v0.x, v0.y, v0.z, v0.w, v1.x, v1.y, v1.z, v1.w};
        union { __nv_bfloat16 h[8]; uint4 q; } uh, ul;
        #pragma unroll
        for (int q = 0; q < 8; ++q) {
            __nv_bfloat16 hi = __float2bfloat16(x[q]);
            uh.h[q] = hi;
            ul.h[q] = __float2bfloat16(x[q] - __bfloat162float(hi));
        }
        uint32_t off = (uint32_t)(row * 1024 + ((c ^ (row & 7)) << 4));
        *(uint4*)(smem + SM_AHI + off) = uh.q;
        *(uint4*)(smem + SM_ALO + off) = ul.q;
    }
    __syncthreads();

    // lane -> ldmatrix address components
    const int g4 = lane >> 3;
    const int aRowOff = ((g4 & 1) << 3) + (lane & 7);
    const int aCadd   = g4 >> 1;
    const int bRowOff = lane & 7;
    const int bCadd   = (lane >> 3) & 1;

    for (int nc = 0; nc < 4; ++nc) {
        const int n0 = nc * NCH;
        float acc[2][4][4] = {};

        // prefetch k-chunk 0
        {
            for (int task = t; task < 2048; task += 256) {
                int p = task >> 10, rem = task & 1023, n = rem >> 3, c = rem & 7;
                const __nv_bfloat16* base = p ? &g_Wt_lo[0][0] : &g_Wt_hi[0][0];
                const char* src = (const char*)base + ((size_t)(n0 + n) * HID + c * 8) * 2;
                uint32_t dst = sb + SM_B + p * 16384 + n * 128 + ((c ^ (n & 7)) << 4);
                cp16(dst, src);
            }
            CP_COMMIT();
        }

        for (int kc = 0; kc < 8; ++kc) {
            if (kc < 7) {
                int kn = kc + 1;
                uint32_t bufn = SM_B + (kn & 1) * 32768;
                for (int task = t; task < 2048; task += 256) {
                    int p = task >> 10, rem = task & 1023, n = rem >> 3, c = rem & 7;
                    const __nv_bfloat16* base = p ? &g_Wt_lo[0][0] : &g_Wt_hi[0][0];
                    const char* src = (const char*)base +
                        ((size_t)(n0 + n) * HID + kn * KCH + c * 8) * 2;
                    uint32_t dst = sb + bufn + p * 16384 + n * 128 + ((c ^ (n & 7)) << 4);
                    cp16(dst, src);
                }
                CP_COMMIT();
                CP_WAIT1();
            } else {
                CP_WAIT0();
            }
            __syncthreads();

            const uint32_t bb = sb + SM_B + (kc & 1) * 32768;
            #pragma unroll
            for (int ks = 0; ks < 4; ++ks) {
                const int ckA = kc * 8 + ks * 2;
                uint32_t Ah[2][4], Al[2][4], Bh[4][2], Bl[4][2];
                #pragma unroll
                for (int mt = 0; mt < 2; ++mt) {
                    int row = warpM * 32 + mt * 16 + aRowOff;
                    uint32_t ca = (uint32_t)((ckA + aCadd) ^ (row & 7));
                    uint32_t ad = sb + SM_AHI + row * 1024 + (ca << 4);
                    ldsm_x4(Ah[mt], ad);
                    ldsm_x4(Al[mt], ad + 65536);
                }
                #pragma unroll
                for (int nt = 0; nt < 4; ++nt) {
                    int nrow = warpN * 32 + nt * 8 + bRowOff;
                    uint32_t cb = (uint32_t)((ks * 2 + bCadd) ^ (nrow & 7));
                    uint32_t bd = bb + nrow * 128 + (cb << 4);
                    ldsm_x2(Bh[nt], bd);
                    ldsm_x2(Bl[nt], bd + 16384);
                }
                #pragma unroll
                for (int mt = 0; mt < 2; ++mt)
                    #pragma unroll
                    for (int nt = 0; nt < 4; ++nt) {
                        mma_bf16(acc[mt][nt], Ah[mt], Bh[nt]);
                        mma_bf16(acc[mt][nt], Al[mt], Bh[nt]);
                        mma_bf16(acc[mt][nt], Ah[mt], Bl[nt]);
                    }
            }
            __syncthreads();
        }

        // ---- epilogue: tanh(acc+bias)*cw, reduce this N-chunk into rs ----
        #pragma unroll
        for (int mt = 0; mt < 2; ++mt) {
            float s0 = 0.f, s1 = 0.f;
            #pragma unroll
            for (int nt = 0; nt < 4; ++nt) {
                int c0 = n0 + warpN * 32 + nt * 8 + (lane & 3) * 2;
                float b0 = sbias[c0], b1 = sbias[c0 + 1];
                float w0 = scw[c0],   w1 = scw[c0 + 1];
                s0 += fast_tanh(acc[mt][nt][0] + b0) * w0
                    + fast_tanh(acc[mt][nt][1] + b1) * w1;
                s1 += fast_tanh(acc[mt][nt][2] + b0) * w0
                    + fast_tanh(acc[mt][nt][3] + b1) * w1;
            }
            s0 += __shfl_xor_sync(0xffffffffu, s0, 1);
            s0 += __shfl_xor_sync(0xffffffffu, s0, 2);
            s1 += __shfl_xor_sync(0xffffffffu, s1, 1);
            s1 += __shfl_xor_sync(0xffffffffu, s1, 2);
            if ((lane & 3) == 0) {
                int r = warpM * 32 + mt * 16 + (lane >> 2);
                atomicAdd(&rs[r], s0);
                atomicAdd(&rs[r + 8], s1);
            }
        }
    }

    __syncthreads();
    if (t < MT) g_scores[row0 + t] = fast_tanh(rs[t]);
}

// ---------------------------------------------------------------------------
// Softmax stats + zero ctx. grid = B, 256 threads.
// ---------------------------------------------------------------------------
__global__ __launch_bounds__(256) void stats_kernel()
{
    const int b = blockIdx.x;
    const int t = threadIdx.x;
    __shared__ float red[256];

    float m = -1e30f;
    for (int i = t; i < Tlen; i += 256) m = fmaxf(m, g_scores[b * Tlen + i]);
    red[t] = m; __syncthreads();
    for (int s = 128; s > 0; s >>= 1) {
        if (t < s) red[t] = fmaxf(red[t], red[t + s]);
        __syncthreads();
    }
    const float mx = red[0];
    __syncthreads();

    float sum = 0.f;
    for (int i = t; i < Tlen; i += 256) sum += __expf(g_scores[b * Tlen + i] - mx);
    red[t] = sum; __syncthreads();
    for (int s = 128; s > 0; s >>= 1) {
        if (t < s) red[t] += red[t + s];
        __syncthreads();
    }
    if (t == 0) { g_rowmax[b] = mx; g_rowsum[b] = red[0]; }

    for (int i = t; i < HID; i += 256) g_ctx[b * HID + i] = 0.f;
}

// ---------------------------------------------------------------------------
// ctx[b,h] += sum_t attn * emb. grid = (B, 8), 512 threads.
// ---------------------------------------------------------------------------
#define TCH 8
#define TPC (Tlen / TCH)   // 256

__global__ __launch_bounds__(512) void ctx_kernel(const float* __restrict__ emb)
{
    const int b  = blockIdx.x;
    const int ck = blockIdx.y;
    const int h  = threadIdx.x;
    __shared__ float wsh[TPC];

    const int t0 = ck * TPC;
    if (h < TPC) {
        const float mx  = g_rowmax[b];
        const float inv = __frcp_rn(g_rowsum[b]);
        wsh[h] = __expf(g_scores[b * Tlen + t0 + h] - mx) * inv;
    }
    __syncthreads();

    float acc = 0.f;
    const float* e = emb + ((size_t)b * Tlen + t0) * HID + h;
    #pragma unroll 8
    for (int tt = 0; tt < TPC; ++tt)
        acc += wsh[tt] * e[(size_t)tt * HID];

    atomicAdd(&g_ctx[b * HID + h], acc);
}

// ---------------------------------------------------------------------------
// Hidden layer: relu(ctx@W1+b1). grid = (B, 4), 256 threads.
// ---------------------------------------------------------------------------
__global__ __launch_bounds__(256) void hidden_kernel(
    const float* __restrict__ W1, const float* __restrict__ b1)
{
    const int b = blockIdx.x;
    const int j = blockIdx.y * 256 + threadIdx.x;
    __shared__ float sc[HID];
    for (int i = threadIdx.x; i < HID; i += 256) sc[i] = g_ctx[b * HID + i];
    __syncthreads();

    float a = __ldg(&b1[j]);
    #pragma unroll 8
    for (int h = 0; h < HID; ++h)
        a += sc[h] * __ldg(&W1[(size_t)h * HCLS + j]);
    g_hidden[b * HCLS + j] = fmaxf(a, 0.f);
}

// ---------------------------------------------------------------------------
// Logits + softmax. grid = B, 256 threads.
// ---------------------------------------------------------------------------
__global__ __launch_bounds__(256) void logits_kernel(
    const float* __restrict__ W2, const float* __restrict__ b2,
    float* __restrict__ out)
{
    const int b = blockIdx.x;
    const int t = threadIdx.x;
    __shared__ float red[256];
    __shared__ float logits[DOUT];

    float p[DOUT];
    #pragma unroll
    for (int o = 0; o < DOUT; ++o) p[o] = 0.f;

    for (int h = t; h < HCLS; h += 256) {
        float hv = g_hidden[b * HCLS + h];
        #pragma unroll
        for (int o = 0; o < DOUT; ++o)
            p[o] += hv * __ldg(&W2[(size_t)h * DOUT + o]);
    }
    #pragma unroll
    for (int o = 0; o < DOUT; ++o) {
        red[t] = p[o]; __syncthreads();
        for (int s = 128; s > 0; s >>= 1) {
            if (t < s) red[t] += red[t + s];
            __syncthreads();
        }
        if (t == 0) logits[o] = red[0] + __ldg(&b2[o]);
        __syncthreads();
    }

    if (t == 0) {
        float mx = -1e30f;
        #pragma unroll
        for (int o = 0; o < DOUT; ++o) mx = fmaxf(mx, logits[o]);
        float s = 0.f, ex[DOUT];
        #pragma unroll
        for (int o = 0; o < DOUT; ++o) { ex[o] = __expf(logits[o] - mx); s += ex[o]; }
        const float inv = 1.f / s;
        #pragma unroll
        for (int o = 0; o < DOUT; ++o) out[b * DOUT + o] = ex[o] * inv;
    }
}

// ---------------------------------------------------------------------------
// Launch. Inputs: numerical, embedding, weight, bias, context_weight,
// W1, b1, W2, b2. Output: [B, DOUT] float32.
// ---------------------------------------------------------------------------
extern "C" void kernel_launch(void* const* d_in, const int* in_sizes, int n_in,
                              void* d_out, int out_size)
{
    (void)in_sizes; (void)n_in; (void)out_size;
    const float* emb  = (const float*)d_in[1];
    const float* W    = (const float*)d_in[2];
    const float* bias = (const float*)d_in[3];
    const float* cw   = (const float*)d_in[4];
    const float* W1   = (const float*)d_in[5];
    const float* b1   = (const float*)d_in[6];
    const float* W2   = (const float*)d_in[7];
    const float* b2   = (const float*)d_in[8];
    float* out = (float*)d_out;

    static bool attr_set = false;
    if (!attr_set) {
        cudaFuncSetAttribute(scores_kernel,
                             cudaFuncAttributeMaxDynamicSharedMemorySize, SM_TOTAL);
        attr_set = true;
    }

    prep_kernel<<<(HID * HID) / 512, 512>>>(W);
    scores_kernel<<<(Bsz * Tlen) / MT, 256, SM_TOTAL>>>(emb, bias, cw);
    stats_kernel<<<Bsz, 256>>>();
    ctx_kernel<<<dim3(Bsz, TCH), 512>>>(emb);
    hidden_kernel<<<dim3(Bsz, HCLS / 256), 256>>>(W1, b1);
    logits_kernel<<<Bsz, 256>>>(W2, b2, out);
}

// round 4
// speedup vs baseline: 3.1891x; 1.3313x over previous
#include <cuda_runtime.h>
#include <cuda_fp16.h>
#include <cstdint>

// ---------------- problem constants ----------------
#define Bsz   64
#define Tlen  2048
#define HID   512
#define HCLS  1024
#define DOUT  10

// ---------------- GEMM tiling ----------------
#define MT    64          // rows per CTA
#define NCH   128         // N per chunk (4 chunks cover 512)
#define KCH   64          // K per cp.async chunk

// ---------------- device scratch ----------------
__device__ __align__(16) __half g_Wt_hi[HID][HID];   // W^T fp16 plane [n][k]
__device__ float g_scores[Bsz * Tlen];
__device__ float g_rowmax[Bsz];
__device__ float g_rowsum[Bsz];
__device__ float g_ctx[Bsz * HID];
__device__ float g_hidden[Bsz * HCLS];

// ---------------- SMEM layout (dynamic) ----------------
#define SM_AHI   0                       // 64 KB (64 x 512 fp16, swizzled)
#define SM_ALO   65536                   // 64 KB
#define SM_B     131072                  // 2 buffers x 16384 = 32 KB
#define SM_BIAS  163840
#define SM_CW    165888
#define SM_RS    167936
#define SM_TOTAL 168192

// ---------------- helpers ----------------
__device__ __forceinline__ float fast_tanh(float x) {
    x = fminf(fmaxf(x, -15.f), 15.f);
    float e = __expf(2.f * x);
    return __fdividef(e - 1.f, e + 1.f);
}

__device__ __forceinline__ uint32_t smem_u32(const void* p) {
    uint32_t a;
    asm("{ .reg .u64 t; cvta.to.shared.u64 t, %1; cvt.u32.u64 %0, t; }" : "=r"(a) : "l"(p));
    return a;
}

__device__ __forceinline__ void ldsm_x4(uint32_t* r, uint32_t addr) {
    asm volatile("ldmatrix.sync.aligned.m8n8.x4.shared.b16 {%0,%1,%2,%3}, [%4];"
                 : "=r"(r[0]), "=r"(r[1]), "=r"(r[2]), "=r"(r[3]) : "r"(addr));
}
__device__ __forceinline__ void ldsm_x2(uint32_t* r, uint32_t addr) {
    asm volatile("ldmatrix.sync.aligned.m8n8.x2.shared.b16 {%0,%1}, [%2];"
                 : "=r"(r[0]), "=r"(r[1]) : "r"(addr));
}
__device__ __forceinline__ void mma_f16(float* d, const uint32_t* a, const uint32_t* b) {
    asm volatile("mma.sync.aligned.m16n8k16.row.col.f32.f16.f16.f32 "
                 "{%0,%1,%2,%3}, {%4,%5,%6,%7}, {%8,%9}, {%0,%1,%2,%3};"
                 : "+f"(d[0]), "+f"(d[1]), "+f"(d[2]), "+f"(d[3])
                 : "r"(a[0]), "r"(a[1]), "r"(a[2]), "r"(a[3]), "r"(b[0]), "r"(b[1]));
}
__device__ __forceinline__ void cp16(uint32_t dst, const void* gsrc) {
    uint64_t g = __cvta_generic_to_global((void*)gsrc);
    asm volatile("cp.async.ca.shared.global [%0], [%1], 16;" :: "r"(dst), "l"(g) : "memory");
}
#define CP_COMMIT() asm volatile("cp.async.commit_group;" ::: "memory")
#define CP_WAIT0()  asm volatile("cp.async.wait_group 0;" ::: "memory")
#define CP_WAIT1()  asm volatile("cp.async.wait_group 1;" ::: "memory")

// ---------------------------------------------------------------------------
// Prep: W[k][n] fp32 -> W^T[n][k] fp16 (hi plane only; the dropped A*B_lo
// correction contributes ~6e-5 relative error to u, far under threshold).
// ---------------------------------------------------------------------------
__global__ __launch_bounds__(512) void prep_kernel(const float* __restrict__ W)
{
    int idx = blockIdx.x * 512 + threadIdx.x;   // 0..262143
    int n = idx & 511;
    int k = idx >> 9;
    g_Wt_hi[n][k] = __float2half_rn(W[(size_t)k * HID + n]);
}

// ---------------------------------------------------------------------------
// Scores: 64 rows/CTA, mma.sync fp16 2-pass (A_hi + A_lo, B_hi only),
// fused tanh-dot-tanh epilogue.
// 256 threads = 8 warps as 2(M) x 4(N); warp tile 32x32 (2 m16 x 4 n8).
// ---------------------------------------------------------------------------
__global__ __launch_bounds__(256, 1) void scores_kernel(
    const float* __restrict__ emb,
    const float* __restrict__ bias,
    const float* __restrict__ cw)
{
    extern __shared__ char smem[];
    const uint32_t sb = smem_u32(smem);
    const int t    = threadIdx.x;
    const int wid  = t >> 5;
    const int lane = t & 31;
    const int warpM = wid >> 2;      // 0..1
    const int warpN = wid & 3;       // 0..3
    const int row0 = blockIdx.x * MT;

    float* sbias = (float*)(smem + SM_BIAS);
    float* scw   = (float*)(smem + SM_CW);
    float* rs    = (float*)(smem + SM_RS);

    for (int i = t; i < HID; i += 256) { sbias[i] = bias[i]; scw[i] = cw[i]; }
    if (t < MT) rs[t] = 0.f;

    // ---- A: load 64x512 fp32, split fp16 hi/lo, store swizzled (once) ----
    for (int task = t; task < MT * 64; task += 256) {
        int row = task >> 6;
        int c   = task & 63;                     // 16B chunk (8 fp16)
        const float4* src = (const float4*)&emb[(size_t)(row0 + row) * HID + c * 8];
        float4 v0 = src[0], v1 = src[1];
        float x[8] = {v0.x, v0.y, v0.z, v0.w, v1.x, v1.y, v1.z, v1.w};
        union { __half h[8]; uint4 q; } uh, ul;
        #pragma unroll
        for (int q = 0; q < 8; ++q) {
            __half hi = __float2half_rn(x[q]);
            uh.h[q] = hi;
            ul.h[q] = __float2half_rn(x[q] - __half2float(hi));
        }
        uint32_t off = (uint32_t)(row * 1024 + ((c ^ (row & 7)) << 4));
        *(uint4*)(smem + SM_AHI + off) = uh.q;
        *(uint4*)(smem + SM_ALO + off) = ul.q;
    }
    __syncthreads();

    // lane -> ldmatrix address components
    const int g4 = lane >> 3;
    const int aRowOff = ((g4 & 1) << 3) + (lane & 7);
    const int aCadd   = g4 >> 1;
    const int bRowOff = lane & 7;
    const int bCadd   = (lane >> 3) & 1;

    for (int nc = 0; nc < 4; ++nc) {
        const int n0 = nc * NCH;
        float acc[2][4][4] = {};

        // prefetch k-chunk 0 (B hi tile: 128 n x 64 k fp16 = 16 KB)
        {
            for (int task = t; task < 1024; task += 256) {
                int n = task >> 3, c = task & 7;
                const char* src = (const char*)&g_Wt_hi[0][0] +
                    ((size_t)(n0 + n) * HID + c * 8) * 2;
                uint32_t dst = sb + SM_B + n * 128 + ((c ^ (n & 7)) << 4);
                cp16(dst, src);
            }
            CP_COMMIT();
        }

        for (int kc = 0; kc < 8; ++kc) {
            if (kc < 7) {
                int kn = kc + 1;
                uint32_t bufn = SM_B + (kn & 1) * 16384;
                for (int task = t; task < 1024; task += 256) {
                    int n = task >> 3, c = task & 7;
                    const char* src = (const char*)&g_Wt_hi[0][0] +
                        ((size_t)(n0 + n) * HID + kn * KCH + c * 8) * 2;
                    uint32_t dst = sb + bufn + n * 128 + ((c ^ (n & 7)) << 4);
                    cp16(dst, src);
                }
                CP_COMMIT();
                CP_WAIT1();
            } else {
                CP_WAIT0();
            }
            __syncthreads();

            const uint32_t bb = sb + SM_B + (kc & 1) * 16384;
            #pragma unroll
            for (int ks = 0; ks < 4; ++ks) {
                const int ckA = kc * 8 + ks * 2;
                uint32_t Ah[2][4], Al[2][4], Bh[4][2];
                #pragma unroll
                for (int mt = 0; mt < 2; ++mt) {
                    int row = warpM * 32 + mt * 16 + aRowOff;
                    uint32_t ca = (uint32_t)((ckA + aCadd) ^ (row & 7));
                    uint32_t ad = sb + SM_AHI + row * 1024 + (ca << 4);
                    ldsm_x4(Ah[mt], ad);
                    ldsm_x4(Al[mt], ad + 65536);
                }
                #pragma unroll
                for (int nt = 0; nt < 4; ++nt) {
                    int nrow = warpN * 32 + nt * 8 + bRowOff;
                    uint32_t cb = (uint32_t)((ks * 2 + bCadd) ^ (nrow & 7));
                    ldsm_x2(Bh[nt], bb + nrow * 128 + (cb << 4));
                }
                #pragma unroll
                for (int mt = 0; mt < 2; ++mt)
                    #pragma unroll
                    for (int nt = 0; nt < 4; ++nt) {
                        mma_f16(acc[mt][nt], Ah[mt], Bh[nt]);
                        mma_f16(acc[mt][nt], Al[mt], Bh[nt]);
                    }
            }
            __syncthreads();
        }

        // ---- epilogue: tanh(acc+bias)*cw, reduce this N-chunk into rs ----
        #pragma unroll
        for (int mt = 0; mt < 2; ++mt) {
            float s0 = 0.f, s1 = 0.f;
            #pragma unroll
            for (int nt = 0; nt < 4; ++nt) {
                int c0 = n0 + warpN * 32 + nt * 8 + (lane & 3) * 2;
                float b0 = sbias[c0], b1 = sbias[c0 + 1];
                float w0 = scw[c0],   w1 = scw[c0 + 1];
                s0 += fast_tanh(acc[mt][nt][0] + b0) * w0
                    + fast_tanh(acc[mt][nt][1] + b1) * w1;
                s1 += fast_tanh(acc[mt][nt][2] + b0) * w0
                    + fast_tanh(acc[mt][nt][3] + b1) * w1;
            }
            s0 += __shfl_xor_sync(0xffffffffu, s0, 1);
            s0 += __shfl_xor_sync(0xffffffffu, s0, 2);
            s1 += __shfl_xor_sync(0xffffffffu, s1, 1);
            s1 += __shfl_xor_sync(0xffffffffu, s1, 2);
            if ((lane & 3) == 0) {
                int r = warpM * 32 + mt * 16 + (lane >> 2);
                atomicAdd(&rs[r], s0);
                atomicAdd(&rs[r + 8], s1);
            }
        }
    }

    __syncthreads();
    if (t < MT) g_scores[row0 + t] = fast_tanh(rs[t]);
}

// ---------------------------------------------------------------------------
// Softmax stats + zero ctx. grid = B, 256 threads.
// ---------------------------------------------------------------------------
__global__ __launch_bounds__(256) void stats_kernel()
{
    const int b = blockIdx.x;
    const int t = threadIdx.x;
    __shared__ float red[256];

    float m = -1e30f;
    for (int i = t; i < Tlen; i += 256) m = fmaxf(m, g_scores[b * Tlen + i]);
    red[t] = m; __syncthreads();
    for (int s = 128; s > 0; s >>= 1) {
        if (t < s) red[t] = fmaxf(red[t], red[t + s]);
        __syncthreads();
    }
    const float mx = red[0];
    __syncthreads();

    float sum = 0.f;
    for (int i = t; i < Tlen; i += 256) sum += __expf(g_scores[b * Tlen + i] - mx);
    red[t] = sum; __syncthreads();
    for (int s = 128; s > 0; s >>= 1) {
        if (t < s) red[t] += red[t + s];
        __syncthreads();
    }
    if (t == 0) { g_rowmax[b] = mx; g_rowsum[b] = red[0]; }

    for (int i = t; i < HID; i += 256) g_ctx[b * HID + i] = 0.f;
}

// ---------------------------------------------------------------------------
// ctx[b,h] += sum_t attn * emb. grid = (B, 8), 512 threads.
// ---------------------------------------------------------------------------
#define TCH 8
#define TPC (Tlen / TCH)   // 256

__global__ __launch_bounds__(512) void ctx_kernel(const float* __restrict__ emb)
{
    const int b  = blockIdx.x;
    const int ck = blockIdx.y;
    const int h  = threadIdx.x;
    __shared__ float wsh[TPC];

    const int t0 = ck * TPC;
    if (h < TPC) {
        const float mx  = g_rowmax[b];
        const float inv = __frcp_rn(g_rowsum[b]);
        wsh[h] = __expf(g_scores[b * Tlen + t0 + h] - mx) * inv;
    }
    __syncthreads();

    float acc = 0.f;
    const float* e = emb + ((size_t)b * Tlen + t0) * HID + h;
    #pragma unroll 8
    for (int tt = 0; tt < TPC; ++tt)
        acc += wsh[tt] * e[(size_t)tt * HID];

    atomicAdd(&g_ctx[b * HID + h], acc);
}

// ---------------------------------------------------------------------------
// Hidden layer: relu(ctx@W1+b1). grid = (B, 4), 256 threads.
// ---------------------------------------------------------------------------
__global__ __launch_bounds__(256) void hidden_kernel(
    const float* __restrict__ W1, const float* __restrict__ b1)
{
    const int b = blockIdx.x;
    const int j = blockIdx.y * 256 + threadIdx.x;
    __shared__ float sc[HID];
    for (int i = threadIdx.x; i < HID; i += 256) sc[i] = g_ctx[b * HID + i];
    __syncthreads();

    float a = __ldg(&b1[j]);
    #pragma unroll 8
    for (int h = 0; h < HID; ++h)
        a += sc[h] * __ldg(&W1[(size_t)h * HCLS + j]);
    g_hidden[b * HCLS + j] = fmaxf(a, 0.f);
}

// ---------------------------------------------------------------------------
// Logits + softmax. grid = B, 256 threads.
// ---------------------------------------------------------------------------
__global__ __launch_bounds__(256) void logits_kernel(
    const float* __restrict__ W2, const float* __restrict__ b2,
    float* __restrict__ out)
{
    const int b = blockIdx.x;
    const int t = threadIdx.x;
    __shared__ float red[256];
    __shared__ float logits[DOUT];

    float p[DOUT];
    #pragma unroll
    for (int o = 0; o < DOUT; ++o) p[o] = 0.f;

    for (int h = t; h < HCLS; h += 256) {
        float hv = g_hidden[b * HCLS + h];
        #pragma unroll
        for (int o = 0; o < DOUT; ++o)
            p[o] += hv * __ldg(&W2[(size_t)h * DOUT + o]);
    }
    #pragma unroll
    for (int o = 0; o < DOUT; ++o) {
        red[t] = p[o]; __syncthreads();
        for (int s = 128; s > 0; s >>= 1) {
            if (t < s) red[t] += red[t + s];
            __syncthreads();
        }
        if (t == 0) logits[o] = red[0] + __ldg(&b2[o]);
        __syncthreads();
    }

    if (t == 0) {
        float mx = -1e30f;
        #pragma unroll
        for (int o = 0; o < DOUT; ++o) mx = fmaxf(mx, logits[o]);
        float s = 0.f, ex[DOUT];
        #pragma unroll
        for (int o = 0; o < DOUT; ++o) { ex[o] = __expf(logits[o] - mx); s += ex[o]; }
        const float inv = 1.f / s;
        #pragma unroll
        for (int o = 0; o < DOUT; ++o) out[b * DOUT + o] = ex[o] * inv;
    }
}

// ---------------------------------------------------------------------------
// Launch. Inputs: numerical, embedding, weight, bias, context_weight,
// W1, b1, W2, b2. Output: [B, DOUT] float32.
// ---------------------------------------------------------------------------
extern "C" void kernel_launch(void* const* d_in, const int* in_sizes, int n_in,
                              void* d_out, int out_size)
{
    (void)in_sizes; (void)n_in; (void)out_size;
    const float* emb  = (const float*)d_in[1];
    const float* W    = (const float*)d_in[2];
    const float* bias = (const float*)d_in[3];
    const float* cw   = (const float*)d_in[4];
    const float* W1   = (const float*)d_in[5];
    const float* b1   = (const float*)d_in[6];
    const float* W2   = (const float*)d_in[7];
    const float* b2   = (const float*)d_in[8];
    float* out = (float*)d_out;

    static bool attr_set = false;
    if (!attr_set) {
        cudaFuncSetAttribute(scores_kernel,
                             cudaFuncAttributeMaxDynamicSharedMemorySize, SM_TOTAL);
        attr_set = true;
    }

    prep_kernel<<<(HID * HID) / 512, 512>>>(W);
    scores_kernel<<<(Bsz * Tlen) / MT, 256, SM_TOTAL>>>(emb, bias, cw);
    stats_kernel<<<Bsz, 256>>>();
    ctx_kernel<<<dim3(Bsz, TCH), 512>>>(emb);
    hidden_kernel<<<dim3(Bsz, HCLS / 256), 256>>>(W1, b1);
    logits_kernel<<<Bsz, 256>>>(W2, b2, out);
}

// round 5
// speedup vs baseline: 5.3717x; 1.6844x over previous
#include <cuda_runtime.h>
#include <cuda_fp16.h>
#include <cstdint>

// ---------------- problem constants ----------------
#define Bsz   64
#define Tlen  2048
#define HID   512
#define HCLS  1024
#define DOUT  10

// ---------------- GEMM tiling ----------------
#define MT    64          // rows per CTA
#define NCH   128         // N per chunk (4 chunks cover 512)
#define KCH   64          // K per cp.async chunk

// ---------------- device scratch ----------------
__device__ __align__(16) __half g_Wt_hi[HID][HID];   // W^T fp16 [n][k]
__device__ float g_scores[Bsz * Tlen];
__device__ float g_rowmax[Bsz];
__device__ float g_rowsum[Bsz];
__device__ float g_ctx[Bsz * HID];
__device__ float g_hidden[Bsz * HCLS];

// ---------------- SMEM layout (dynamic) ----------------
#define SM_A     0                       // 64 KB (64 x 512 fp16, swizzled)
#define SM_B     65536                   // 2 buffers x 16384 = 32 KB
#define SM_BIAS  98304
#define SM_CW    100352
#define SM_RS    102400
#define SM_TOTAL 102656

// ---------------- helpers ----------------
__device__ __forceinline__ float fast_tanh(float x) {
    x = fminf(fmaxf(x, -15.f), 15.f);
    float e = __expf(2.f * x);
    return __fdividef(e - 1.f, e + 1.f);
}

__device__ __forceinline__ uint32_t smem_u32(const void* p) {
    uint32_t a;
    asm("{ .reg .u64 t; cvta.to.shared.u64 t, %1; cvt.u32.u64 %0, t; }" : "=r"(a) : "l"(p));
    return a;
}

__device__ __forceinline__ void ldsm_x4(uint32_t* r, uint32_t addr) {
    asm volatile("ldmatrix.sync.aligned.m8n8.x4.shared.b16 {%0,%1,%2,%3}, [%4];"
                 : "=r"(r[0]), "=r"(r[1]), "=r"(r[2]), "=r"(r[3]) : "r"(addr));
}
__device__ __forceinline__ void ldsm_x2(uint32_t* r, uint32_t addr) {
    asm volatile("ldmatrix.sync.aligned.m8n8.x2.shared.b16 {%0,%1}, [%2];"
                 : "=r"(r[0]), "=r"(r[1]) : "r"(addr));
}
__device__ __forceinline__ void mma_f16(float* d, const uint32_t* a, const uint32_t* b) {
    asm volatile("mma.sync.aligned.m16n8k16.row.col.f32.f16.f16.f32 "
                 "{%0,%1,%2,%3}, {%4,%5,%6,%7}, {%8,%9}, {%0,%1,%2,%3};"
                 : "+f"(d[0]), "+f"(d[1]), "+f"(d[2]), "+f"(d[3])
                 : "r"(a[0]), "r"(a[1]), "r"(a[2]), "r"(a[3]), "r"(b[0]), "r"(b[1]));
}
__device__ __forceinline__ void cp16(uint32_t dst, const void* gsrc) {
    uint64_t g = __cvta_generic_to_global((void*)gsrc);
    asm volatile("cp.async.ca.shared.global [%0], [%1], 16;" :: "r"(dst), "l"(g) : "memory");
}
#define CP_COMMIT() asm volatile("cp.async.commit_group;" ::: "memory")
#define CP_WAIT0()  asm volatile("cp.async.wait_group 0;" ::: "memory")
#define CP_WAIT1()  asm volatile("cp.async.wait_group 1;" ::: "memory")

// ---------------------------------------------------------------------------
// Prep: W[k][n] fp32 -> W^T[n][k] fp16.
// ---------------------------------------------------------------------------
__global__ __launch_bounds__(512) void prep_kernel(const float* __restrict__ W)
{
    int idx = blockIdx.x * 512 + threadIdx.x;   // 0..262143
    int n = idx & 511;
    int k = idx >> 9;
    g_Wt_hi[n][k] = __float2half_rn(W[(size_t)k * HID + n]);
}

// ---------------------------------------------------------------------------
// Scores: 64 rows/CTA, single-pass fp16 mma.sync, fused tanh-dot-tanh epilogue.
// 256 threads = 8 warps as 2(M) x 4(N); warp tile 32x32. 2 CTAs/SM.
// ---------------------------------------------------------------------------
__global__ __launch_bounds__(256, 2) void scores_kernel(
    const float* __restrict__ emb,
    const float* __restrict__ bias,
    const float* __restrict__ cw)
{
    extern __shared__ char smem[];
    const uint32_t sb = smem_u32(smem);
    const int t    = threadIdx.x;
    const int wid  = t >> 5;
    const int lane = t & 31;
    const int warpM = wid >> 2;      // 0..1
    const int warpN = wid & 3;       // 0..3
    const int row0 = blockIdx.x * MT;

    float* sbias = (float*)(smem + SM_BIAS);
    float* scw   = (float*)(smem + SM_CW);
    float* rs    = (float*)(smem + SM_RS);

    for (int i = t; i < HID; i += 256) { sbias[i] = bias[i]; scw[i] = cw[i]; }
    if (t < MT) rs[t] = 0.f;

    // ---- A: load 64x512 fp32, convert fp16, store swizzled (once) ----
    for (int task = t; task < MT * 64; task += 256) {
        int row = task >> 6;
        int c   = task & 63;                     // 16B chunk (8 fp16)
        const float4* src = (const float4*)&emb[(size_t)(row0 + row) * HID + c * 8];
        float4 v0 = src[0], v1 = src[1];
        float x[8] = {v0.x, v0.y, v0.z, v0.w, v1.x, v1.y, v1.z, v1.w};
        union { __half h[8]; uint4 q; } uh;
        #pragma unroll
        for (int q = 0; q < 8; ++q) uh.h[q] = __float2half_rn(x[q]);
        uint32_t off = (uint32_t)(row * 1024 + ((c ^ (row & 7)) << 4));
        *(uint4*)(smem + SM_A + off) = uh.q;
    }
    __syncthreads();

    // lane -> ldmatrix address components
    const int g4 = lane >> 3;
    const int aRowOff = ((g4 & 1) << 3) + (lane & 7);
    const int aCadd   = g4 >> 1;
    const int bRowOff = lane & 7;
    const int bCadd   = (lane >> 3) & 1;

    for (int nc = 0; nc < 4; ++nc) {
        const int n0 = nc * NCH;
        float acc[2][4][4] = {};

        // prefetch k-chunk 0 (B tile: 128 n x 64 k fp16 = 16 KB)
        {
            for (int task = t; task < 1024; task += 256) {
                int n = task >> 3, c = task & 7;
                const char* src = (const char*)&g_Wt_hi[0][0] +
                    ((size_t)(n0 + n) * HID + c * 8) * 2;
                uint32_t dst = sb + SM_B + n * 128 + ((c ^ (n & 7)) << 4);
                cp16(dst, src);
            }
            CP_COMMIT();
        }

        for (int kc = 0; kc < 8; ++kc) {
            if (kc < 7) {
                int kn = kc + 1;
                uint32_t bufn = SM_B + (kn & 1) * 16384;
                for (int task = t; task < 1024; task += 256) {
                    int n = task >> 3, c = task & 7;
                    const char* src = (const char*)&g_Wt_hi[0][0] +
                        ((size_t)(n0 + n) * HID + kn * KCH + c * 8) * 2;
                    uint32_t dst = sb + bufn + n * 128 + ((c ^ (n & 7)) << 4);
                    cp16(dst, src);
                }
                CP_COMMIT();
                CP_WAIT1();
            } else {
                CP_WAIT0();
            }
            __syncthreads();

            const uint32_t bb = sb + SM_B + (kc & 1) * 16384;
            #pragma unroll
            for (int ks = 0; ks < 4; ++ks) {
                const int ckA = kc * 8 + ks * 2;
                uint32_t Ah[2][4], Bh[4][2];
                #pragma unroll
                for (int mt = 0; mt < 2; ++mt) {
                    int row = warpM * 32 + mt * 16 + aRowOff;
                    uint32_t ca = (uint32_t)((ckA + aCadd) ^ (row & 7));
                    ldsm_x4(Ah[mt], sb + SM_A + row * 1024 + (ca << 4));
                }
                #pragma unroll
                for (int nt = 0; nt < 4; ++nt) {
                    int nrow = warpN * 32 + nt * 8 + bRowOff;
                    uint32_t cb = (uint32_t)((ks * 2 + bCadd) ^ (nrow & 7));
                    ldsm_x2(Bh[nt], bb + nrow * 128 + (cb << 4));
                }
                #pragma unroll
                for (int mt = 0; mt < 2; ++mt)
                    #pragma unroll
                    for (int nt = 0; nt < 4; ++nt)
                        mma_f16(acc[mt][nt], Ah[mt], Bh[nt]);
            }
            __syncthreads();
        }

        // ---- epilogue: tanh(acc+bias)*cw, reduce this N-chunk into rs ----
        #pragma unroll
        for (int mt = 0; mt < 2; ++mt) {
            float s0 = 0.f, s1 = 0.f;
            #pragma unroll
            for (int nt = 0; nt < 4; ++nt) {
                int c0 = n0 + warpN * 32 + nt * 8 + (lane & 3) * 2;
                float b0 = sbias[c0], b1 = sbias[c0 + 1];
                float w0 = scw[c0],   w1 = scw[c0 + 1];
                s0 += fast_tanh(acc[mt][nt][0] + b0) * w0
                    + fast_tanh(acc[mt][nt][1] + b1) * w1;
                s1 += fast_tanh(acc[mt][nt][2] + b0) * w0
                    + fast_tanh(acc[mt][nt][3] + b1) * w1;
            }
            s0 += __shfl_xor_sync(0xffffffffu, s0, 1);
            s0 += __shfl_xor_sync(0xffffffffu, s0, 2);
            s1 += __shfl_xor_sync(0xffffffffu, s1, 1);
            s1 += __shfl_xor_sync(0xffffffffu, s1, 2);
            if ((lane & 3) == 0) {
                int r = warpM * 32 + mt * 16 + (lane >> 2);
                atomicAdd(&rs[r], s0);
                atomicAdd(&rs[r + 8], s1);
            }
        }
    }

    __syncthreads();
    if (t < MT) g_scores[row0 + t] = fast_tanh(rs[t]);
}

// ---------------------------------------------------------------------------
// Softmax stats + zero ctx. grid = B, 256 threads.
// ---------------------------------------------------------------------------
__global__ __launch_bounds__(256) void stats_kernel()
{
    const int b = blockIdx.x;
    const int t = threadIdx.x;
    __shared__ float red[256];

    float m = -1e30f;
    for (int i = t; i < Tlen; i += 256) m = fmaxf(m, g_scores[b * Tlen + i]);
    red[t] = m; __syncthreads();
    for (int s = 128; s > 0; s >>= 1) {
        if (t < s) red[t] = fmaxf(red[t], red[t + s]);
        __syncthreads();
    }
    const float mx = red[0];
    __syncthreads();

    float sum = 0.f;
    for (int i = t; i < Tlen; i += 256) sum += __expf(g_scores[b * Tlen + i] - mx);
    red[t] = sum; __syncthreads();
    for (int s = 128; s > 0; s >>= 1) {
        if (t < s) red[t] += red[t + s];
        __syncthreads();
    }
    if (t == 0) { g_rowmax[b] = mx; g_rowsum[b] = red[0]; }

    for (int i = t; i < HID; i += 256) g_ctx[b * HID + i] = 0.f;
}

// ---------------------------------------------------------------------------
// ctx[b,h] += sum_t attn * emb. grid = (B, 16), 512 threads.
// ---------------------------------------------------------------------------
#define TCH 16
#define TPC (Tlen / TCH)   // 128

__global__ __launch_bounds__(512) void ctx_kernel(const float* __restrict__ emb)
{
    const int b  = blockIdx.x;
    const int ck = blockIdx.y;
    const int h  = threadIdx.x;
    __shared__ float wsh[TPC];

    const int t0 = ck * TPC;
    if (h < TPC) {
        const float mx  = g_rowmax[b];
        const float inv = __frcp_rn(g_rowsum[b]);
        wsh[h] = __expf(g_scores[b * Tlen + t0 + h] - mx) * inv;
    }
    __syncthreads();

    float acc = 0.f;
    const float* e = emb + ((size_t)b * Tlen + t0) * HID + h;
    #pragma unroll 8
    for (int tt = 0; tt < TPC; ++tt)
        acc += wsh[tt] * e[(size_t)tt * HID];

    atomicAdd(&g_ctx[b * HID + h], acc);
}

// ---------------------------------------------------------------------------
// Hidden layer: relu(ctx@W1+b1). grid = (B, 4), 256 threads.
// ---------------------------------------------------------------------------
__global__ __launch_bounds__(256) void hidden_kernel(
    const float* __restrict__ W1, const float* __restrict__ b1)
{
    const int b = blockIdx.x;
    const int j = blockIdx.y * 256 + threadIdx.x;
    __shared__ float sc[HID];
    for (int i = threadIdx.x; i < HID; i += 256) sc[i] = g_ctx[b * HID + i];
    __syncthreads();

    float a = __ldg(&b1[j]);
    #pragma unroll 8
    for (int h = 0; h < HID; ++h)
        a += sc[h] * __ldg(&W1[(size_t)h * HCLS + j]);
    g_hidden[b * HCLS + j] = fmaxf(a, 0.f);
}

// ---------------------------------------------------------------------------
// Logits + softmax. grid = B, 256 threads.
// ---------------------------------------------------------------------------
__global__ __launch_bounds__(256) void logits_kernel(
    const float* __restrict__ W2, const float* __restrict__ b2,
    float* __restrict__ out)
{
    const int b = blockIdx.x;
    const int t = threadIdx.x;
    __shared__ float red[256];
    __shared__ float logits[DOUT];

    float p[DOUT];
    #pragma unroll
    for (int o = 0; o < DOUT; ++o) p[o] = 0.f;

    for (int h = t; h < HCLS; h += 256) {
        float hv = g_hidden[b * HCLS + h];
        #pragma unroll
        for (int o = 0; o < DOUT; ++o)
            p[o] += hv * __ldg(&W2[(size_t)h * DOUT + o]);
    }
    #pragma unroll
    for (int o = 0; o < DOUT; ++o) {
        red[t] = p[o]; __syncthreads();
        for (int s = 128; s > 0; s >>= 1) {
            if (t < s) red[t] += red[t + s];
            __syncthreads();
        }
        if (t == 0) logits[o] = red[0] + __ldg(&b2[o]);
        __syncthreads();
    }

    if (t == 0) {
        float mx = -1e30f;
        #pragma unroll
        for (int o = 0; o < DOUT; ++o) mx = fmaxf(mx, logits[o]);
        float s = 0.f, ex[DOUT];
        #pragma unroll
        for (int o = 0; o < DOUT; ++o) { ex[o] = __expf(logits[o] - mx); s += ex[o]; }
        const float inv = 1.f / s;
        #pragma unroll
        for (int o = 0; o < DOUT; ++o) out[b * DOUT + o] = ex[o] * inv;
    }
}

// ---------------------------------------------------------------------------
// Launch. Inputs: numerical, embedding, weight, bias, context_weight,
// W1, b1, W2, b2. Output: [B, DOUT] float32.
// ---------------------------------------------------------------------------
extern "C" void kernel_launch(void* const* d_in, const int* in_sizes, int n_in,
                              void* d_out, int out_size)
{
    (void)in_sizes; (void)n_in; (void)out_size;
    const float* emb  = (const float*)d_in[1];
    const float* W    = (const float*)d_in[2];
    const float* bias = (const float*)d_in[3];
    const float* cw   = (const float*)d_in[4];
    const float* W1   = (const float*)d_in[5];
    const float* b1   = (const float*)d_in[6];
    const float* W2   = (const float*)d_in[7];
    const float* b2   = (const float*)d_in[8];
    float* out = (float*)d_out;

    static bool attr_set = false;
    if (!attr_set) {
        cudaFuncSetAttribute(scores_kernel,
                             cudaFuncAttributeMaxDynamicSharedMemorySize, SM_TOTAL);
        attr_set = true;
    }

    prep_kernel<<<(HID * HID) / 512, 512>>>(W);
    scores_kernel<<<(Bsz * Tlen) / MT, 256, SM_TOTAL>>>(emb, bias, cw);
    stats_kernel<<<Bsz, 256>>>();
    ctx_kernel<<<dim3(Bsz, TCH), 512>>>(emb);
    hidden_kernel<<<dim3(Bsz, HCLS / 256), 256>>>(W1, b1);
    logits_kernel<<<Bsz, 256>>>(W2, b2, out);
}

// round 6
// speedup vs baseline: 5.5461x; 1.0325x over previous
#include <cuda_runtime.h>
#include <cuda_fp16.h>
#include <cstdint>

// ---------------- problem constants ----------------
#define Bsz   64
#define Tlen  2048
#define HID   512
#define HCLS  1024
#define DOUT  10

// ---------------- GEMM tiling ----------------
#define MT    64          // rows per CTA
#define NCH   128         // N per chunk (4 chunks cover 512)
#define KCH   64          // K per cp.async chunk
#define NCTA  ((Bsz * Tlen) / MT)      // 2048
#define CPB   (Tlen / MT)              // 32 chunks per batch

// ---------------- device scratch ----------------
__device__ __align__(16) __half g_Wt_hi[HID][HID];   // W^T fp16 [n][k]
__device__ float g_pctx[NCTA * HID];                 // per-chunk partial ctx (4 MB)
__device__ float g_m[NCTA];                          // per-chunk local max
__device__ float g_s[NCTA];                          // per-chunk local sumexp
__device__ float g_ctx[Bsz * HID];
__device__ float g_hidden[Bsz * HCLS];

// ---------------- SMEM layout (dynamic) ----------------
#define SM_A     0                       // 64 KB (64 x 512 fp16, swizzled)
#define SM_B     65536                   // 2 buffers x 16384 = 32 KB
#define SM_BIAS  98304
#define SM_CW    100352
#define SM_RS    102400                  // 64 floats: pre-tanh row sums
#define SM_PW    102656                  // 64 floats: softmax chunk weights
#define SM_RED   102912                  // 64 floats: reductions
#define SM_TOTAL 103168

// ---------------- helpers ----------------
__device__ __forceinline__ float fast_tanh(float x) {
    x = fminf(fmaxf(x, -15.f), 15.f);
    float e = __expf(2.f * x);
    return __fdividef(e - 1.f, e + 1.f);
}

__device__ __forceinline__ uint32_t smem_u32(const void* p) {
    uint32_t a;
    asm("{ .reg .u64 t; cvta.to.shared.u64 t, %1; cvt.u32.u64 %0, t; }" : "=r"(a) : "l"(p));
    return a;
}

__device__ __forceinline__ void ldsm_x4(uint32_t* r, uint32_t addr) {
    asm volatile("ldmatrix.sync.aligned.m8n8.x4.shared.b16 {%0,%1,%2,%3}, [%4];"
                 : "=r"(r[0]), "=r"(r[1]), "=r"(r[2]), "=r"(r[3]) : "r"(addr));
}
__device__ __forceinline__ void ldsm_x2(uint32_t* r, uint32_t addr) {
    asm volatile("ldmatrix.sync.aligned.m8n8.x2.shared.b16 {%0,%1}, [%2];"
                 : "=r"(r[0]), "=r"(r[1]) : "r"(addr));
}
__device__ __forceinline__ void mma_f16(float* d, const uint32_t* a, const uint32_t* b) {
    asm volatile("mma.sync.aligned.m16n8k16.row.col.f32.f16.f16.f32 "
                 "{%0,%1,%2,%3}, {%4,%5,%6,%7}, {%8,%9}, {%0,%1,%2,%3};"
                 : "+f"(d[0]), "+f"(d[1]), "+f"(d[2]), "+f"(d[3])
                 : "r"(a[0]), "r"(a[1]), "r"(a[2]), "r"(a[3]), "r"(b[0]), "r"(b[1]));
}
__device__ __forceinline__ void cp16(uint32_t dst, const void* gsrc) {
    uint64_t g = __cvta_generic_to_global((void*)gsrc);
    asm volatile("cp.async.ca.shared.global [%0], [%1], 16;" :: "r"(dst), "l"(g) : "memory");
}
#define CP_COMMIT() asm volatile("cp.async.commit_group;" ::: "memory")
#define CP_WAIT0()  asm volatile("cp.async.wait_group 0;" ::: "memory")
#define CP_WAIT1()  asm volatile("cp.async.wait_group 1;" ::: "memory")

// ---------------------------------------------------------------------------
// Prep: W[k][n] fp32 -> W^T[n][k] fp16.
// ---------------------------------------------------------------------------
__global__ __launch_bounds__(512) void prep_kernel(const float* __restrict__ W)
{
    int idx = blockIdx.x * 512 + threadIdx.x;   // 0..262143
    int n = idx & 511;
    int k = idx >> 9;
    g_Wt_hi[n][k] = __float2half_rn(W[(size_t)k * HID + n]);
}

// ---------------------------------------------------------------------------
// Scores + local softmax + partial ctx. 64 rows/CTA (one T-chunk of one batch).
// 256 threads = 8 warps as 2(M) x 4(N); warp tile 32x32; 2 CTAs/SM.
// Epilogue re-reads this CTA's emb tile (L2-hot) for the weighted sum.
// ---------------------------------------------------------------------------
__global__ __launch_bounds__(256, 2) void scores_kernel(
    const float* __restrict__ emb,
    const float* __restrict__ bias,
    const float* __restrict__ cw)
{
    extern __shared__ char smem[];
    const uint32_t sb = smem_u32(smem);
    const int t    = threadIdx.x;
    const int wid  = t >> 5;
    const int lane = t & 31;
    const int warpM = wid >> 2;      // 0..1
    const int warpN = wid & 3;       // 0..3
    const int row0 = blockIdx.x * MT;

    float* sbias = (float*)(smem + SM_BIAS);
    float* scw   = (float*)(smem + SM_CW);
    float* rs    = (float*)(smem + SM_RS);
    float* pw    = (float*)(smem + SM_PW);
    float* red   = (float*)(smem + SM_RED);

    for (int i = t; i < HID; i += 256) { sbias[i] = bias[i]; scw[i] = cw[i]; }
    if (t < MT) rs[t] = 0.f;

    // ---- A: load 64x512 fp32, convert fp16, store swizzled (once) ----
    for (int task = t; task < MT * 64; task += 256) {
        int row = task >> 6;
        int c   = task & 63;                     // 16B chunk (8 fp16)
        const float4* src = (const float4*)&emb[(size_t)(row0 + row) * HID + c * 8];
        float4 v0 = src[0], v1 = src[1];
        float x[8] = {v0.x, v0.y, v0.z, v0.w, v1.x, v1.y, v1.z, v1.w};
        union { __half h[8]; uint4 q; } uh;
        #pragma unroll
        for (int q = 0; q < 8; ++q) uh.h[q] = __float2half_rn(x[q]);
        uint32_t off = (uint32_t)(row * 1024 + ((c ^ (row & 7)) << 4));
        *(uint4*)(smem + SM_A + off) = uh.q;
    }
    __syncthreads();

    // lane -> ldmatrix address components
    const int g4 = lane >> 3;
    const int aRowOff = ((g4 & 1) << 3) + (lane & 7);
    const int aCadd   = g4 >> 1;
    const int bRowOff = lane & 7;
    const int bCadd   = (lane >> 3) & 1;

    for (int nc = 0; nc < 4; ++nc) {
        const int n0 = nc * NCH;
        float acc[2][4][4] = {};

        // prefetch k-chunk 0 (B tile: 128 n x 64 k fp16 = 16 KB)
        {
            for (int task = t; task < 1024; task += 256) {
                int n = task >> 3, c = task & 7;
                const char* src = (const char*)&g_Wt_hi[0][0] +
                    ((size_t)(n0 + n) * HID + c * 8) * 2;
                uint32_t dst = sb + SM_B + n * 128 + ((c ^ (n & 7)) << 4);
                cp16(dst, src);
            }
            CP_COMMIT();
        }

        for (int kc = 0; kc < 8; ++kc) {
            if (kc < 7) {
                int kn = kc + 1;
                uint32_t bufn = SM_B + (kn & 1) * 16384;
                for (int task = t; task < 1024; task += 256) {
                    int n = task >> 3, c = task & 7;
                    const char* src = (const char*)&g_Wt_hi[0][0] +
                        ((size_t)(n0 + n) * HID + kn * KCH + c * 8) * 2;
                    uint32_t dst = sb + bufn + n * 128 + ((c ^ (n & 7)) << 4);
                    cp16(dst, src);
                }
                CP_COMMIT();
                CP_WAIT1();
            } else {
                CP_WAIT0();
            }
            __syncthreads();

            const uint32_t bb = sb + SM_B + (kc & 1) * 16384;
            #pragma unroll
            for (int ks = 0; ks < 4; ++ks) {
                const int ckA = kc * 8 + ks * 2;
                uint32_t Ah[2][4], Bh[4][2];
                #pragma unroll
                for (int mt = 0; mt < 2; ++mt) {
                    int row = warpM * 32 + mt * 16 + aRowOff;
                    uint32_t ca = (uint32_t)((ckA + aCadd) ^ (row & 7));
                    ldsm_x4(Ah[mt], sb + SM_A + row * 1024 + (ca << 4));
                }
                #pragma unroll
                for (int nt = 0; nt < 4; ++nt) {
                    int nrow = warpN * 32 + nt * 8 + bRowOff;
                    uint32_t cb = (uint32_t)((ks * 2 + bCadd) ^ (nrow & 7));
                    ldsm_x2(Bh[nt], bb + nrow * 128 + (cb << 4));
                }
                #pragma unroll
                for (int mt = 0; mt < 2; ++mt)
                    #pragma unroll
                    for (int nt = 0; nt < 4; ++nt)
                        mma_f16(acc[mt][nt], Ah[mt], Bh[nt]);
            }
            __syncthreads();
        }

        // ---- tanh(acc+bias)*cw, reduce this N-chunk into rs ----
        #pragma unroll
        for (int mt = 0; mt < 2; ++mt) {
            float s0 = 0.f, s1 = 0.f;
            #pragma unroll
            for (int nt = 0; nt < 4; ++nt) {
                int c0 = n0 + warpN * 32 + nt * 8 + (lane & 3) * 2;
                float b0 = sbias[c0], b1 = sbias[c0 + 1];
                float w0 = scw[c0],   w1 = scw[c0 + 1];
                s0 += fast_tanh(acc[mt][nt][0] + b0) * w0
                    + fast_tanh(acc[mt][nt][1] + b1) * w1;
                s1 += fast_tanh(acc[mt][nt][2] + b0) * w0
                    + fast_tanh(acc[mt][nt][3] + b1) * w1;
            }
            s0 += __shfl_xor_sync(0xffffffffu, s0, 1);
            s0 += __shfl_xor_sync(0xffffffffu, s0, 2);
            s1 += __shfl_xor_sync(0xffffffffu, s1, 1);
            s1 += __shfl_xor_sync(0xffffffffu, s1, 2);
            if ((lane & 3) == 0) {
                int r = warpM * 32 + mt * 16 + (lane >> 2);
                atomicAdd(&rs[r], s0);
                atomicAdd(&rs[r + 8], s1);
            }
        }
    }
    __syncthreads();

    // ---- local softmax over this chunk's 64 scores ----
    if (t < MT) red[t] = fast_tanh(rs[t]);
    __syncthreads();
    if (t < MT) rs[t] = red[t];          // rs now holds the scores
    // max reduce over 64 (two warps via shfl, combine in smem)
    if (t < MT) {
        float v = rs[t];
        #pragma unroll
        for (int o = 16; o > 0; o >>= 1) v = fmaxf(v, __shfl_xor_sync(0xffffffffu, v, o));
        if (lane == 0) red[wid] = v;
    }
    __syncthreads();
    const float mloc = fmaxf(red[0], red[1]);
    if (t < MT) pw[t] = __expf(rs[t] - mloc);
    __syncthreads();
    if (t < MT) {
        float v = pw[t];
        #pragma unroll
        for (int o = 16; o > 0; o >>= 1) v += __shfl_xor_sync(0xffffffffu, v, o);
        if (lane == 0) red[8 + wid] = v;
    }
    __syncthreads();
    if (t == 0) {
        g_m[blockIdx.x] = mloc;
        g_s[blockIdx.x] = red[8] + red[9];
    }

    // ---- partial ctx: pctx[h] = sum_t pw[t] * emb[row0+t][h] (L2-hot reads) ----
    {
        float a0 = 0.f, a1 = 0.f;
        const float* e = emb + (size_t)row0 * HID + t;
        #pragma unroll 4
        for (int tt = 0; tt < MT; ++tt) {
            float w = pw[tt];
            a0 += w * e[(size_t)tt * HID];
            a1 += w * e[(size_t)tt * HID + 256];
        }
        g_pctx[(size_t)blockIdx.x * HID + t]       = a0;
        g_pctx[(size_t)blockIdx.x * HID + t + 256] = a1;
    }
}

// ---------------------------------------------------------------------------
// Combine: ctx[b,h] = sum_c e^{m_c-M} pctx_c[h] / sum_c e^{m_c-M} s_c.
// grid = B, 512 threads.
// ---------------------------------------------------------------------------
__global__ __launch_bounds__(512) void combine_kernel()
{
    const int b = blockIdx.x;
    const int t = threadIdx.x;
    __shared__ float wexp[CPB];
    __shared__ float sden;

    if (t < 32) {
        float m = g_m[b * CPB + t];
        float M = m;
        #pragma unroll
        for (int o = 16; o > 0; o >>= 1) M = fmaxf(M, __shfl_xor_sync(0xffffffffu, M, o));
        float w = __expf(m - M);
        wexp[t] = w;
        float d = w * g_s[b * CPB + t];
        #pragma unroll
        for (int o = 16; o > 0; o >>= 1) d += __shfl_xor_sync(0xffffffffu, d, o);
        if (t == 0) sden = d;
    }
    __syncthreads();

    const float inv = __frcp_rn(sden);
    float acc = 0.f;
    #pragma unroll 4
    for (int c = 0; c < CPB; ++c)
        acc += wexp[c] * g_pctx[((size_t)(b * CPB + c)) * HID + t];
    g_ctx[b * HID + t] = acc * inv;
}

// ---------------------------------------------------------------------------
// Hidden layer: relu(ctx@W1+b1). grid = (B, 4), 256 threads.
// ---------------------------------------------------------------------------
__global__ __launch_bounds__(256) void hidden_kernel(
    const float* __restrict__ W1, const float* __restrict__ b1)
{
    const int b = blockIdx.x;
    const int j = blockIdx.y * 256 + threadIdx.x;
    __shared__ float sc[HID];
    for (int i = threadIdx.x; i < HID; i += 256) sc[i] = g_ctx[b * HID + i];
    __syncthreads();

    float a = __ldg(&b1[j]);
    #pragma unroll 8
    for (int h = 0; h < HID; ++h)
        a += sc[h] * __ldg(&W1[(size_t)h * HCLS + j]);
    g_hidden[b * HCLS + j] = fmaxf(a, 0.f);
}

// ---------------------------------------------------------------------------
// Logits + softmax. grid = B, 256 threads.
// ---------------------------------------------------------------------------
__global__ __launch_bounds__(256) void logits_kernel(
    const float* __restrict__ W2, const float* __restrict__ b2,
    float* __restrict__ out)
{
    const int b = blockIdx.x;
    const int t = threadIdx.x;
    __shared__ float red[256];
    __shared__ float logits[DOUT];

    float p[DOUT];
    #pragma unroll
    for (int o = 0; o < DOUT; ++o) p[o] = 0.f;

    for (int h = t; h < HCLS; h += 256) {
        float hv = g_hidden[b * HCLS + h];
        #pragma unroll
        for (int o = 0; o < DOUT; ++o)
            p[o] += hv * __ldg(&W2[(size_t)h * DOUT + o]);
    }
    #pragma unroll
    for (int o = 0; o < DOUT; ++o) {
        red[t] = p[o]; __syncthreads();
        for (int s = 128; s > 0; s >>= 1) {
            if (t < s) red[t] += red[t + s];
            __syncthreads();
        }
        if (t == 0) logits[o] = red[0] + __ldg(&b2[o]);
        __syncthreads();
    }

    if (t == 0) {
        float mx = -1e30f;
        #pragma unroll
        for (int o = 0; o < DOUT; ++o) mx = fmaxf(mx, logits[o]);
        float s = 0.f, ex[DOUT];
        #pragma unroll
        for (int o = 0; o < DOUT; ++o) { ex[o] = __expf(logits[o] - mx); s += ex[o]; }
        const float inv = 1.f / s;
        #pragma unroll
        for (int o = 0; o < DOUT; ++o) out[b * DOUT + o] = ex[o] * inv;
    }
}

// ---------------------------------------------------------------------------
// Launch. Inputs: numerical, embedding, weight, bias, context_weight,
// W1, b1, W2, b2. Output: [B, DOUT] float32.
// ---------------------------------------------------------------------------
extern "C" void kernel_launch(void* const* d_in, const int* in_sizes, int n_in,
                              void* d_out, int out_size)
{
    (void)in_sizes; (void)n_in; (void)out_size;
    const float* emb  = (const float*)d_in[1];
    const float* W    = (const float*)d_in[2];
    const float* bias = (const float*)d_in[3];
    const float* cw   = (const float*)d_in[4];
    const float* W1   = (const float*)d_in[5];
    const float* b1   = (const float*)d_in[6];
    const float* W2   = (const float*)d_in[7];
    const float* b2   = (const float*)d_in[8];
    float* out = (float*)d_out;

    static bool attr_set = false;
    if (!attr_set) {
        cudaFuncSetAttribute(scores_kernel,
                             cudaFuncAttributeMaxDynamicSharedMemorySize, SM_TOTAL);
        attr_set = true;
    }

    prep_kernel<<<(HID * HID) / 512, 512>>>(W);
    scores_kernel<<<NCTA, 256, SM_TOTAL>>>(emb, bias, cw);
    combine_kernel<<<Bsz, 512>>>();
    hidden_kernel<<<dim3(Bsz, HCLS / 256), 256>>>(W1, b1);
    logits_kernel<<<Bsz, 256>>>(W2, b2, out);
}

// round 7
// speedup vs baseline: 5.9737x; 1.0771x over previous
#include <cuda_runtime.h>
#include <cuda_fp16.h>
#include <cstdint>

// ---------------- problem constants ----------------
#define Bsz   64
#define Tlen  2048
#define HID   512
#define HCLS  1024
#define DOUT  10

// ---------------- GEMM tiling ----------------
#define MT    64          // rows per CTA
#define NCH   128         // N per chunk (4 chunks cover 512)
#define KCH   64          // K per cp.async chunk
#define NCTA  ((Bsz * Tlen) / MT)      // 2048
#define CPB   (Tlen / MT)              // 32 chunks per batch

// ---------------- device scratch ----------------
__device__ __align__(16) __half g_Wt_hi[HID][HID];   // W^T fp16 [n][k]
__device__ float g_pctx[NCTA * HID];                 // per-chunk partial ctx (4 MB)
__device__ float g_m[NCTA];                          // per-chunk local max
__device__ float g_s[NCTA];                          // per-chunk local sumexp
__device__ float g_ctx[Bsz * HID];
__device__ float g_hidden[Bsz * HCLS];               // pre-activation (atomic acc)

// ---------------- SMEM layout (dynamic) ----------------
#define SM_A     0                       // 64 KB (64 x 512 fp16, swizzled)
#define SM_B     65536                   // 2 buffers x 16384 = 32 KB
#define SM_BIAS  98304
#define SM_CW    100352
#define SM_RS    102400                  // 64 floats: pre-tanh row sums
#define SM_PW    102656                  // 64 floats: softmax chunk weights
#define SM_RED   102912                  // 64 floats: reductions
#define SM_TOTAL 103168

// ---------------- helpers ----------------
__device__ __forceinline__ float fast_tanh(float x) {
    x = fminf(fmaxf(x, -15.f), 15.f);
    float e = __expf(2.f * x);
    return __fdividef(e - 1.f, e + 1.f);
}

__device__ __forceinline__ uint32_t smem_u32(const void* p) {
    uint32_t a;
    asm("{ .reg .u64 t; cvta.to.shared.u64 t, %1; cvt.u32.u64 %0, t; }" : "=r"(a) : "l"(p));
    return a;
}

__device__ __forceinline__ void ldsm_x4(uint32_t* r, uint32_t addr) {
    asm volatile("ldmatrix.sync.aligned.m8n8.x4.shared.b16 {%0,%1,%2,%3}, [%4];"
                 : "=r"(r[0]), "=r"(r[1]), "=r"(r[2]), "=r"(r[3]) : "r"(addr));
}
__device__ __forceinline__ void ldsm_x2(uint32_t* r, uint32_t addr) {
    asm volatile("ldmatrix.sync.aligned.m8n8.x2.shared.b16 {%0,%1}, [%2];"
                 : "=r"(r[0]), "=r"(r[1]) : "r"(addr));
}
__device__ __forceinline__ void mma_f16(float* d, const uint32_t* a, const uint32_t* b) {
    asm volatile("mma.sync.aligned.m16n8k16.row.col.f32.f16.f16.f32 "
                 "{%0,%1,%2,%3}, {%4,%5,%6,%7}, {%8,%9}, {%0,%1,%2,%3};"
                 : "+f"(d[0]), "+f"(d[1]), "+f"(d[2]), "+f"(d[3])
                 : "r"(a[0]), "r"(a[1]), "r"(a[2]), "r"(a[3]), "r"(b[0]), "r"(b[1]));
}
__device__ __forceinline__ void cp16(uint32_t dst, const void* gsrc) {
    uint64_t g = __cvta_generic_to_global((void*)gsrc);
    asm volatile("cp.async.ca.shared.global [%0], [%1], 16;" :: "r"(dst), "l"(g) : "memory");
}
#define CP_COMMIT() asm volatile("cp.async.commit_group;" ::: "memory")
#define CP_WAIT0()  asm volatile("cp.async.wait_group 0;" ::: "memory")
#define CP_WAIT1()  asm volatile("cp.async.wait_group 1;" ::: "memory")

// ---------------------------------------------------------------------------
// Prep: W[k][n] fp32 -> W^T[n][k] fp16 via SMEM tile transpose (coalesced
// both ways). Also zeroes g_hidden. grid = 64 blocks x 256 threads.
// ---------------------------------------------------------------------------
__global__ __launch_bounds__(256) void prep_kernel(const float* __restrict__ W)
{
    __shared__ __half tile[64][65];
    const int bk = (blockIdx.x >> 3) * 64;    // k tile origin
    const int bn = (blockIdx.x & 7) * 64;     // n tile origin
    const int t = threadIdx.x;

    {   // load 64x64 fp32 tile (coalesced), convert, store to smem
        int r  = t >> 2;               // k within tile
        int c0 = (t & 3) * 16;         // n within tile
        const float4* src = (const float4*)&W[(size_t)(bk + r) * HID + bn + c0];
        #pragma unroll
        for (int q = 0; q < 4; ++q) {
            float4 v = src[q];
            tile[r][c0 + q*4 + 0] = __float2half_rn(v.x);
            tile[r][c0 + q*4 + 1] = __float2half_rn(v.y);
            tile[r][c0 + q*4 + 2] = __float2half_rn(v.z);
            tile[r][c0 + q*4 + 3] = __float2half_rn(v.w);
        }
    }
    __syncthreads();
    {   // write transposed: 16 consecutive k per thread = 32B contiguous
        int n  = t >> 2;
        int k0 = (t & 3) * 16;
        union { __half h[16]; uint4 q[2]; } o;
        #pragma unroll
        for (int i = 0; i < 16; ++i) o.h[i] = tile[k0 + i][n];
        uint4* dst = (uint4*)&g_Wt_hi[bn + n][bk + k0];
        dst[0] = o.q[0];
        dst[1] = o.q[1];
    }
    // zero hidden pre-activation accumulator (64 blocks x 256 = 16384 threads)
    for (int i = blockIdx.x * 256 + t; i < Bsz * HCLS; i += 64 * 256)
        g_hidden[i] = 0.f;
}

// ---------------------------------------------------------------------------
// Scores + local softmax + partial ctx. 64 rows/CTA; 2 CTAs/SM.
// ---------------------------------------------------------------------------
__global__ __launch_bounds__(256, 2) void scores_kernel(
    const float* __restrict__ emb,
    const float* __restrict__ bias,
    const float* __restrict__ cw)
{
    extern __shared__ char smem[];
    const uint32_t sb = smem_u32(smem);
    const int t    = threadIdx.x;
    const int wid  = t >> 5;
    const int lane = t & 31;
    const int warpM = wid >> 2;      // 0..1
    const int warpN = wid & 3;       // 0..3
    const int row0 = blockIdx.x * MT;

    float* sbias = (float*)(smem + SM_BIAS);
    float* scw   = (float*)(smem + SM_CW);
    float* rs    = (float*)(smem + SM_RS);
    float* pw    = (float*)(smem + SM_PW);
    float* red   = (float*)(smem + SM_RED);

    for (int i = t; i < HID; i += 256) { sbias[i] = bias[i]; scw[i] = cw[i]; }
    if (t < MT) rs[t] = 0.f;

    // ---- A: load 64x512 fp32, convert fp16, store swizzled (once) ----
    for (int task = t; task < MT * 64; task += 256) {
        int row = task >> 6;
        int c   = task & 63;                     // 16B chunk (8 fp16)
        const float4* src = (const float4*)&emb[(size_t)(row0 + row) * HID + c * 8];
        float4 v0 = src[0], v1 = src[1];
        float x[8] = {v0.x, v0.y, v0.z, v0.w, v1.x, v1.y, v1.z, v1.w};
        union { __half h[8]; uint4 q; } uh;
        #pragma unroll
        for (int q = 0; q < 8; ++q) uh.h[q] = __float2half_rn(x[q]);
        uint32_t off = (uint32_t)(row * 1024 + ((c ^ (row & 7)) << 4));
        *(uint4*)(smem + SM_A + off) = uh.q;
    }
    __syncthreads();

    // lane -> ldmatrix address components
    const int g4 = lane >> 3;
    const int aRowOff = ((g4 & 1) << 3) + (lane & 7);
    const int aCadd   = g4 >> 1;
    const int bRowOff = lane & 7;
    const int bCadd   = (lane >> 3) & 1;

    for (int nc = 0; nc < 4; ++nc) {
        const int n0 = nc * NCH;
        float acc[2][4][4] = {};

        // prefetch k-chunk 0 (B tile: 128 n x 64 k fp16 = 16 KB)
        {
            for (int task = t; task < 1024; task += 256) {
                int n = task >> 3, c = task & 7;
                const char* src = (const char*)&g_Wt_hi[0][0] +
                    ((size_t)(n0 + n) * HID + c * 8) * 2;
                uint32_t dst = sb + SM_B + n * 128 + ((c ^ (n & 7)) << 4);
                cp16(dst, src);
            }
            CP_COMMIT();
        }

        for (int kc = 0; kc < 8; ++kc) {
            if (kc < 7) {
                int kn = kc + 1;
                uint32_t bufn = SM_B + (kn & 1) * 16384;
                for (int task = t; task < 1024; task += 256) {
                    int n = task >> 3, c = task & 7;
                    const char* src = (const char*)&g_Wt_hi[0][0] +
                        ((size_t)(n0 + n) * HID + kn * KCH + c * 8) * 2;
                    uint32_t dst = sb + bufn + n * 128 + ((c ^ (n & 7)) << 4);
                    cp16(dst, src);
                }
                CP_COMMIT();
                CP_WAIT1();
            } else {
                CP_WAIT0();
            }
            __syncthreads();

            const uint32_t bb = sb + SM_B + (kc & 1) * 16384;
            #pragma unroll
            for (int ks = 0; ks < 4; ++ks) {
                const int ckA = kc * 8 + ks * 2;
                uint32_t Ah[2][4], Bh[4][2];
                #pragma unroll
                for (int mt = 0; mt < 2; ++mt) {
                    int row = warpM * 32 + mt * 16 + aRowOff;
                    uint32_t ca = (uint32_t)((ckA + aCadd) ^ (row & 7));
                    ldsm_x4(Ah[mt], sb + SM_A + row * 1024 + (ca << 4));
                }
                #pragma unroll
                for (int nt = 0; nt < 4; ++nt) {
                    int nrow = warpN * 32 + nt * 8 + bRowOff;
                    uint32_t cb = (uint32_t)((ks * 2 + bCadd) ^ (nrow & 7));
                    ldsm_x2(Bh[nt], bb + nrow * 128 + (cb << 4));
                }
                #pragma unroll
                for (int mt = 0; mt < 2; ++mt)
                    #pragma unroll
                    for (int nt = 0; nt < 4; ++nt)
                        mma_f16(acc[mt][nt], Ah[mt], Bh[nt]);
            }
            __syncthreads();
        }

        // ---- tanh(acc+bias)*cw, reduce this N-chunk into rs ----
        #pragma unroll
        for (int mt = 0; mt < 2; ++mt) {
            float s0 = 0.f, s1 = 0.f;
            #pragma unroll
            for (int nt = 0; nt < 4; ++nt) {
                int c0 = n0 + warpN * 32 + nt * 8 + (lane & 3) * 2;
                float b0 = sbias[c0], b1 = sbias[c0 + 1];
                float w0 = scw[c0],   w1 = scw[c0 + 1];
                s0 += fast_tanh(acc[mt][nt][0] + b0) * w0
                    + fast_tanh(acc[mt][nt][1] + b1) * w1;
                s1 += fast_tanh(acc[mt][nt][2] + b0) * w0
                    + fast_tanh(acc[mt][nt][3] + b1) * w1;
            }
            s0 += __shfl_xor_sync(0xffffffffu, s0, 1);
            s0 += __shfl_xor_sync(0xffffffffu, s0, 2);
            s1 += __shfl_xor_sync(0xffffffffu, s1, 1);
            s1 += __shfl_xor_sync(0xffffffffu, s1, 2);
            if ((lane & 3) == 0) {
                int r = warpM * 32 + mt * 16 + (lane >> 2);
                atomicAdd(&rs[r], s0);
                atomicAdd(&rs[r + 8], s1);
            }
        }
    }
    __syncthreads();

    // ---- local softmax over this chunk's 64 scores ----
    if (t < MT) red[t] = fast_tanh(rs[t]);
    __syncthreads();
    if (t < MT) rs[t] = red[t];          // rs now holds the scores
    if (t < MT) {
        float v = rs[t];
        #pragma unroll
        for (int o = 16; o > 0; o >>= 1) v = fmaxf(v, __shfl_xor_sync(0xffffffffu, v, o));
        if (lane == 0) red[wid] = v;
    }
    __syncthreads();
    const float mloc = fmaxf(red[0], red[1]);
    if (t < MT) pw[t] = __expf(rs[t] - mloc);
    __syncthreads();
    if (t < MT) {
        float v = pw[t];
        #pragma unroll
        for (int o = 16; o > 0; o >>= 1) v += __shfl_xor_sync(0xffffffffu, v, o);
        if (lane == 0) red[8 + wid] = v;
    }
    __syncthreads();
    if (t == 0) {
        g_m[blockIdx.x] = mloc;
        g_s[blockIdx.x] = red[8] + red[9];
    }

    // ---- partial ctx: pctx[h] = sum_t pw[t] * emb[row0+t][h] (L2-hot) ----
    {
        float a0 = 0.f, a1 = 0.f;
        const float* e = emb + (size_t)row0 * HID + t;
        #pragma unroll 4
        for (int tt = 0; tt < MT; ++tt) {
            float w = pw[tt];
            a0 += w * e[(size_t)tt * HID];
            a1 += w * e[(size_t)tt * HID + 256];
        }
        g_pctx[(size_t)blockIdx.x * HID + t]       = a0;
        g_pctx[(size_t)blockIdx.x * HID + t + 256] = a1;
    }
}

// ---------------------------------------------------------------------------
// Combine: ctx[b,h] = sum_c e^{m_c-M} pctx_c[h] / sum_c e^{m_c-M} s_c.
// grid = B, 512 threads.
// ---------------------------------------------------------------------------
__global__ __launch_bounds__(512) void combine_kernel()
{
    const int b = blockIdx.x;
    const int t = threadIdx.x;
    __shared__ float wexp[CPB];
    __shared__ float sden;

    if (t < 32) {
        float m = g_m[b * CPB + t];
        float M = m;
        #pragma unroll
        for (int o = 16; o > 0; o >>= 1) M = fmaxf(M, __shfl_xor_sync(0xffffffffu, M, o));
        float w = __expf(m - M);
        wexp[t] = w;
        float d = w * g_s[b * CPB + t];
        #pragma unroll
        for (int o = 16; o > 0; o >>= 1) d += __shfl_xor_sync(0xffffffffu, d, o);
        if (t == 0) sden = d;
    }
    __syncthreads();

    const float inv = __frcp_rn(sden);
    float acc = 0.f;
    #pragma unroll 4
    for (int c = 0; c < CPB; ++c)
        acc += wexp[c] * g_pctx[((size_t)(b * CPB + c)) * HID + t];
    g_ctx[b * HID + t] = acc * inv;
}

// ---------------------------------------------------------------------------
// Hidden layer (pre-activation, split-K): grid (B, 4, 4), 256 threads.
// g_hidden[b,j] += b1[j](ks==0) + sum_{k in chunk} ctx[b,k] W1[k,j].
// ReLU applied at the consumer (logits_kernel).
// ---------------------------------------------------------------------------
#define HKS 4
#define HKC (HID / HKS)   // 128

__global__ __launch_bounds__(256) void hidden_kernel(
    const float* __restrict__ W1, const float* __restrict__ b1)
{
    const int b  = blockIdx.x;
    const int j  = blockIdx.y * 256 + threadIdx.x;
    const int k0 = blockIdx.z * HKC;
    __shared__ float sc[HKC];
    if (threadIdx.x < HKC) sc[threadIdx.x] = g_ctx[b * HID + k0 + threadIdx.x];
    __syncthreads();

    float a = (blockIdx.z == 0) ? __ldg(&b1[j]) : 0.f;
    #pragma unroll 8
    for (int h = 0; h < HKC; ++h)
        a += sc[h] * __ldg(&W1[(size_t)(k0 + h) * HCLS + j]);
    atomicAdd(&g_hidden[b * HCLS + j], a);
}

// ---------------------------------------------------------------------------
// Logits + softmax. grid = B, 1024 threads (one per hidden unit).
// ---------------------------------------------------------------------------
__global__ __launch_bounds__(1024) void logits_kernel(
    const float* __restrict__ W2, const float* __restrict__ b2,
    float* __restrict__ out)
{
    const int b = blockIdx.x;
    const int t = threadIdx.x;
    const int wid = t >> 5;
    const int lane = t & 31;
    __shared__ float part[32][DOUT];

    const float hv = fmaxf(g_hidden[b * HCLS + t], 0.f);
    float p[DOUT];
    #pragma unroll
    for (int o = 0; o < DOUT; ++o) p[o] = hv * __ldg(&W2[(size_t)t * DOUT + o]);

    #pragma unroll
    for (int o = 0; o < DOUT; ++o) {
        #pragma unroll
        for (int s = 16; s > 0; s >>= 1) p[o] += __shfl_xor_sync(0xffffffffu, p[o], s);
    }
    if (lane == 0) {
        #pragma unroll
        for (int o = 0; o < DOUT; ++o) part[wid][o] = p[o];
    }
    __syncthreads();

    if (t < 32) {
        float q[DOUT];
        #pragma unroll
        for (int o = 0; o < DOUT; ++o) q[o] = part[t][o];
        #pragma unroll
        for (int o = 0; o < DOUT; ++o) {
            #pragma unroll
            for (int s = 16; s > 0; s >>= 1) q[o] += __shfl_xor_sync(0xffffffffu, q[o], s);
        }
        if (t == 0) {
            float logits[DOUT];
            float mx = -1e30f;
            #pragma unroll
            for (int o = 0; o < DOUT; ++o) {
                logits[o] = q[o] + __ldg(&b2[o]);
                mx = fmaxf(mx, logits[o]);
            }
            float s = 0.f, ex[DOUT];
            #pragma unroll
            for (int o = 0; o < DOUT; ++o) { ex[o] = __expf(logits[o] - mx); s += ex[o]; }
            const float inv = 1.f / s;
            #pragma unroll
            for (int o = 0; o < DOUT; ++o) out[b * DOUT + o] = ex[o] * inv;
        }
    }
}

// ---------------------------------------------------------------------------
// Launch. Inputs: numerical, embedding, weight, bias, context_weight,
// W1, b1, W2, b2. Output: [B, DOUT] float32.
// ---------------------------------------------------------------------------
extern "C" void kernel_launch(void* const* d_in, const int* in_sizes, int n_in,
                              void* d_out, int out_size)
{
    (void)in_sizes; (void)n_in; (void)out_size;
    const float* emb  = (const float*)d_in[1];
    const float* W    = (const float*)d_in[2];
    const float* bias = (const float*)d_in[3];
    const float* cw   = (const float*)d_in[4];
    const float* W1   = (const float*)d_in[5];
    const float* b1   = (const float*)d_in[6];
    const float* W2   = (const float*)d_in[7];
    const float* b2   = (const float*)d_in[8];
    float* out = (float*)d_out;

    static bool attr_set = false;
    if (!attr_set) {
        cudaFuncSetAttribute(scores_kernel,
                             cudaFuncAttributeMaxDynamicSharedMemorySize, SM_TOTAL);
        attr_set = true;
    }

    prep_kernel<<<64, 256>>>(W);
    scores_kernel<<<NCTA, 256, SM_TOTAL>>>(emb, bias, cw);
    combine_kernel<<<Bsz, 512>>>();
    hidden_kernel<<<dim3(Bsz, HCLS / 256, HKS), 256>>>(W1, b1);
    logits_kernel<<<Bsz, 1024>>>(W2, b2, out);
}